// round 15
// baseline (speedup 1.0000x reference)
#include <cuda_runtime.h>
#include <math.h>

#define QN 1000
#define KN 5
#define MN 50
#define DKN 64
#define DVN 128
#define DSN 50
#define BN 128
#define SN 2048

typedef unsigned long long ull;

// ---------- f32x2 helpers ----------
__device__ __forceinline__ ull ffma2(ull a, ull b, ull c) {
    ull d;
    asm("fma.rn.f32x2 %0, %1, %2, %3;" : "=l"(d) : "l"(a), "l"(b), "l"(c));
    return d;
}
__device__ __forceinline__ ull fpack2(float lo, float hi) {
    ull r;
    asm("mov.b64 %0, {%1, %2};" : "=l"(r) : "f"(lo), "f"(hi));
    return r;
}
__device__ __forceinline__ float2 funpack2(ull v) {
    float2 f;
    asm("mov.b64 {%0, %1}, %2;" : "=f"(f.x), "=f"(f.y) : "l"(v));
    return f;
}

// ---------- scratch ----------
__device__ float g_attn[QN * MN];
__device__ float g_sq[QN * DSN];
__device__ float g_alphat[QN];
__device__ float g_betat[QN * (KN - 1)];
__device__ float g_erase[QN * KN * DVN];
__device__ float g_addt[QN * KN * DVN];
__device__ float g_reads[(size_t)BN * SN * DVN];

// ================= Kernel AB v3: merged tables, 4-way split-k, 512 threads =================
// 1000 CTAs x 512 threads. Thread = (v = t&127, h = t>>7, h in 0..3).
// value-proj: 16 k per thread; erase/add: 32 k per thread (serial chain 128 cyc);
// partials combined via smem. 16 warps/CTA for latency hiding.
__global__ void __launch_bounds__(512)
k_tab(const float* __restrict__ qe_w, const float* __restrict__ key_mem,
      const float* __restrict__ sum_w, const float* __restrict__ sum_b,
      const float* __restrict__ al_w, const float* __restrict__ al_b,
      const float* __restrict__ be_w, const float* __restrict__ be_b,
      const float* __restrict__ item_w,
      const float* __restrict__ vp_w, const float* __restrict__ vp_b,
      const float* __restrict__ er_w, const float* __restrict__ er_b,
      const float* __restrict__ ad_w, const float* __restrict__ ad_b) {
    int q = blockIdx.x;
    int t = threadIdx.x;
    int v = t & 127;
    int h = t >> 7;                 // k-quarter 0..3
    __shared__ float qe[DKN];
    __shared__ float item[DKN];
    __shared__ float sl[MN], se[MN];
    __shared__ float ve[KN][DVN];
    __shared__ float bpart[3][DVN];
    __shared__ float part[3][DVN][2 * KN];

    if (t < DKN) {
        qe[t] = qe_w[q * DKN + t];
        item[t] = item_w[q * DKN + t];
    }
    __syncthreads();

    // ---- phase 1: value-proj base partial (16 k each) + attn logits (h==3) ----
    float pb = (h == 0) ? vp_b[v] : 0.f;
    {
        int k0 = h * 16;
        #pragma unroll
        for (int k = k0; k < k0 + 16; ++k) pb += item[k] * vp_w[k * DVN + v];
    }
    if (h > 0) bpart[h - 1][v] = pb;
    if (h == 3 && v < MN) {
        float acc = 0.f;
        #pragma unroll 8
        for (int k = 0; k < DKN; ++k) acc += qe[k] * key_mem[v * DKN + k];
        sl[v] = acc;
    }
    __syncthreads();

    // ---- phase 2: h0 finalizes ve; h1 softmax exp; h2 sq; h3 alpha/beta ----
    if (h == 0) {
        float base = pb + bpart[0][v] + bpart[1][v] + bpart[2][v];
        #pragma unroll
        for (int r = 0; r < KN; ++r) {
            float acc = base;
            #pragma unroll
            for (int j = 0; j < KN; ++j) {
                float rf = fmaxf(1.f - fabsf((float)j - (float)r) * 0.25f, 0.f);
                acc += rf * vp_w[(DKN + j) * DVN + v];
            }
            ve[r][v] = acc;
        }
    }
    if (h == 1 && v < MN) {
        float mx = -1e30f;
        for (int j = 0; j < MN; ++j) mx = fmaxf(mx, sl[j]);
        se[v] = expf(sl[v] - mx);
    }
    if (h == 2 && v < DSN) {
        float acc = sum_b[v];
        #pragma unroll 8
        for (int k = 0; k < DKN; ++k) acc += qe[k] * sum_w[(DVN + k) * DSN + v];
        g_sq[q * DSN + v] = acc;
    }
    if (h == 3 && v == 0) {
        float acc = al_b[0];
        for (int k = 0; k < DKN; ++k) acc += qe[k] * al_w[k];
        g_alphat[q] = fmaxf(acc, 0.f) + log1pf(expf(-fabsf(acc)));
    }
    if (h == 3 && v >= 8 && v < 8 + KN - 1) {
        int tt = v - 8;
        float acc = be_b[tt];
        for (int k = 0; k < DKN; ++k) acc += qe[k] * be_w[k * (KN - 1) + tt];
        g_betat[q * (KN - 1) + tt] = acc;
    }
    __syncthreads();

    if (h == 1 && v < MN) {
        float sm = 0.f;
        for (int j = 0; j < MN; ++j) sm += se[j];
        g_attn[q * MN + v] = se[v] / sm;
    }

    // ---- phase 3: erase/add accumulation over this thread's k-quarter (32 k) ----
    float e[KN], a[KN];
    float eb = (h == 0) ? er_b[v] : 0.f;
    float ab = (h == 0) ? ad_b[v] : 0.f;
    #pragma unroll
    for (int r = 0; r < KN; ++r) { e[r] = eb; a[r] = ab; }
    {
        int k0 = h * 32;
        #pragma unroll 8
        for (int k = k0; k < k0 + 32; ++k) {
            float ew = er_w[k * DVN + v];
            float aw = ad_w[k * DVN + v];
            #pragma unroll
            for (int r = 0; r < KN; ++r) {
                float vv = ve[r][k];             // broadcast LDS
                e[r] += vv * ew;
                a[r] += vv * aw;
            }
        }
    }
    if (h > 0) {
        #pragma unroll
        for (int r = 0; r < KN; ++r) {
            part[h - 1][v][r] = e[r];
            part[h - 1][v][KN + r] = a[r];
        }
    }
    __syncthreads();
    if (h == 0) {
        #pragma unroll
        for (int r = 0; r < KN; ++r) {
            float er = e[r] + part[0][v][r] + part[1][v][r] + part[2][v][r];
            float ar = a[r] + part[0][v][KN + r] + part[1][v][KN + r] + part[2][v][KN + r];
            g_erase[(q * KN + r) * DVN + v] = 1.f / (1.f + expf(-er));
            g_addt [(q * KN + r) * DVN + v] = tanhf(ar);
        }
    }
}

// ================= Kernel C: scan v8 verbatim (measured best) =================
#define ATT_PAD 52
#define SCAN_SMEM (QN * ATT_PAD * 4 + SN * 4 * 2)

__global__ void __launch_bounds__(256, 1)
k_scan(const int* __restrict__ questions, const int* __restrict__ responses,
       const float* __restrict__ init_mem) {
    extern __shared__ char smem_raw[];
    float* attn_sh = (float*)smem_raw;                       // QN*52 floats
    int*   aoff_sh = (int*)(smem_raw + QN * ATT_PAD * 4);    // q*52 per step
    int*   coff_sh = aoff_sh + SN;                           // (q*5+r)*128 per step

    int b = blockIdx.x, tid = threadIdx.x;
    int wid  = tid >> 5;
    int lane = tid & 31;
    int vsub = lane & 7;
    int mg   = lane >> 3;
    int vp   = wid * 8 + vsub;        // v-pair: v = 2vp, 2vp+1
    int mstart = mg * 13;

    for (int idx = tid; idx < QN * ATT_PAD; idx += 256) {
        int q = idx / ATT_PAD, m = idx - q * ATT_PAD;
        attn_sh[idx] = (m < MN) ? g_attn[q * MN + m] : 0.f;
    }
    for (int i = tid; i < SN; i += 256) {
        int q = questions[b * SN + i];
        int r = responses[b * SN + i];
        aoff_sh[i] = q * ATT_PAD;
        coff_sh[i] = (q * KN + r) * DVN;
    }

    ull mem[13];
    #pragma unroll
    for (int i = 0; i < 13; ++i) {
        int m = mstart + i;
        mem[i] = (m < MN) ? *(const ull*)(init_mem + m * DVN + 2 * vp) : 0ULL;
    }
    __syncthreads();

    // depth-2 erase/add prefetch pipeline
    int c0 = coff_sh[0];
    int c1 = coff_sh[1];
    ull e0  = *(const ull*)(g_erase + c0 + 2 * vp);
    ull ad0 = *(const ull*)(g_addt  + c0 + 2 * vp);
    ull e1  = *(const ull*)(g_erase + c1 + 2 * vp);
    ull ad1 = *(const ull*)(g_addt  + c1 + 2 * vp);

    // attention register prefetch: acur holds step-t row slice
    float acur[13];
    {
        int a0 = aoff_sh[0] + mstart;
        #pragma unroll
        for (int i = 0; i < 13; ++i) acur[i] = attn_sh[a0 + i];
    }

    float* outp = g_reads + (size_t)b * SN * DVN + 2 * vp;

    for (int t0 = 0; t0 < SN; t0 += 8) {
        float bx[8], by[8];
        #pragma unroll
        for (int j = 0; j < 8; ++j) {
            int t = t0 + j;
            ull e_cur = e0, ad_cur = ad0;
            e0 = e1; ad0 = ad1;
            int tp = (t + 2 < SN) ? t + 2 : SN - 1;
            int cp = coff_sh[tp];
            e1  = *(const ull*)(g_erase + cp + 2 * vp);
            ad1 = *(const ull*)(g_addt  + cp + 2 * vp);

            int anx = aoff_sh[(t + 1 < SN) ? t + 1 : SN - 1] + mstart;

            ull neg_e = e_cur ^ 0x8000000080000000ULL;
            ull r0 = 0ULL, r1 = 0ULL;
            #pragma unroll
            for (int i = 0; i < 13; ++i) {
                float a = acur[i];
                acur[i] = attn_sh[anx + i];              // prefetch next step's value
                ull ap = fpack2(a, a);
                ull tmp = ffma2(neg_e, mem[i], ad_cur);  // add - e*mem
                if (i & 1) r1 = ffma2(ap, mem[i], r1);
                else       r0 = ffma2(ap, mem[i], r0);
                mem[i] = ffma2(ap, tmp, mem[i]);         // mem += a*(add - e*mem)
            }
            float2 fa = funpack2(r0), fb = funpack2(r1);
            bx[j] = fa.x + fb.x;
            by[j] = fa.y + fb.y;
        }
        // pipelined reduction burst: 32 independent shfls
        #pragma unroll
        for (int j = 0; j < 8; ++j) {
            bx[j] += __shfl_xor_sync(0xffffffffu, bx[j], 8);
            by[j] += __shfl_xor_sync(0xffffffffu, by[j], 8);
        }
        #pragma unroll
        for (int j = 0; j < 8; ++j) {
            bx[j] += __shfl_xor_sync(0xffffffffu, bx[j], 16);
            by[j] += __shfl_xor_sync(0xffffffffu, by[j], 16);
        }
        if (mg == 0) {
            #pragma unroll
            for (int j = 0; j < 8; ++j)
                *(float2*)(outp + (size_t)(t0 + j) * DVN) = make_float2(bx[j], by[j]);
        }
    }
}

// ================= Kernel D: epilogue v9 verbatim (113.9us measured best) =================
#define TILE_T 256
#define W_STRIDE 26
#define EPI_SMEM ((DVN * W_STRIDE + 4) * 8)

__global__ void __launch_bounds__(256, 2)
k_epi(const int* __restrict__ questions,
      const float* __restrict__ sum_w,
      const float* __restrict__ th_w, const float* __restrict__ th_b,
      float* __restrict__ out) {
    extern __shared__ char smem_raw[];
    ull*   Wsu = (ull*)smem_raw;
    float* Wsf = (float*)Wsu;

    int tid = threadIdx.x;
    int t0 = blockIdx.x * TILE_T;

    // stage Ws (rows 0..127 of summary_w), zero-padded cols 50,51
    for (int i = tid; i < DVN * (2 * W_STRIDE); i += 256) {
        int v = i / (2 * W_STRIDE), j = i - v * (2 * W_STRIDE);
        Wsf[i] = (j < DSN) ? sum_w[v * DSN + j] : 0.f;
    }
    __syncthreads();

    int tg = tid >> 2;        // 0..63
    int jq = tid & 3;         // 0..3
    const float4* rows[4];
    #pragma unroll
    for (int i = 0; i < 4; ++i)
        rows[i] = (const float4*)(g_reads + (size_t)(t0 + tg + 64 * i) * DVN);
    const ull* wbase = Wsu + jq * 7;

    ull acc[4][7];
    #pragma unroll
    for (int i = 0; i < 4; ++i)
        #pragma unroll
        for (int k = 0; k < 7; ++k) acc[i][k] = 0ULL;

    float4 cur[4], nxt[4];
    #pragma unroll
    for (int i = 0; i < 4; ++i) cur[i] = __ldg(rows[i]);

    #pragma unroll 2
    for (int c = 0; c < DVN / 4; ++c) {
        if (c + 1 < DVN / 4) {
            #pragma unroll
            for (int i = 0; i < 4; ++i) nxt[i] = __ldg(rows[i] + c + 1);
        }
        #pragma unroll
        for (int s = 0; s < 4; ++s) {
            const ull* w = wbase + (4 * c + s) * W_STRIDE;
            ull rp[4];
            #pragma unroll
            for (int i = 0; i < 4; ++i) {
                float x = (&cur[i].x)[s];
                rp[i] = fpack2(x, x);
            }
            #pragma unroll
            for (int k = 0; k < 7; ++k) {
                ull wv = w[k];
                #pragma unroll
                for (int i = 0; i < 4; ++i)
                    acc[i][k] = ffma2(rp[i], wv, acc[i][k]);
            }
        }
        #pragma unroll
        for (int i = 0; i < 4; ++i) cur[i] = nxt[i];
    }

    float thb = th_b[0];
    const int N = BN * SN;

    #pragma unroll
    for (int i = 0; i < 4; ++i) {
        int task = t0 + tg + 64 * i;
        int qid = questions[task];
        float thp = 0.f;
        #pragma unroll
        for (int k = 0; k < 7; ++k) {
            int p = jq * 7 + k;
            if (p < 25) {
                float2 ac = funpack2(acc[i][k]);
                float2 sq2 = funpack2(*(const ull*)(g_sq + qid * DSN + 2 * p));
                float2 tw  = funpack2(*(const ull*)(th_w + 2 * p));
                float s0 = tanhf(ac.x + sq2.x);
                float s1 = tanhf(ac.y + sq2.y);
                thp += s0 * tw.x + s1 * tw.y;
            }
        }
        thp += __shfl_xor_sync(0xffffffffu, thp, 1);
        thp += __shfl_xor_sync(0xffffffffu, thp, 2);
        if (jq == 0) {
            float theta = tanhf(thp + thb);
            float alpha = g_alphat[qid];
            float inter = theta * alpha;
            float b0 = g_betat[qid * 4 + 0];
            float b1 = g_betat[qid * 4 + 1];
            float b2 = g_betat[qid * 4 + 2];
            float b3 = g_betat[qid * 4 + 3];
            float l0 = 0.f;
            float l1 = inter - b0;
            float l2 = l1 + inter - b1;
            float l3 = l2 + inter - b2;
            float l4 = l3 + inter - b3;
            float mx = fmaxf(fmaxf(fmaxf(l0, l1), fmaxf(l2, l3)), l4);
            float e0x = expf(l0 - mx), e1x = expf(l1 - mx), e2x = expf(l2 - mx);
            float e3x = expf(l3 - mx), e4x = expf(l4 - mx);
            float inv = 1.f / (e0x + e1x + e2x + e3x + e4x);

            out[task] = theta;
            out[N + task] = alpha;
            float* bo = out + 2 * N + (size_t)task * 4;
            bo[0] = b0; bo[1] = b1; bo[2] = b2; bo[3] = b3;
            float* lo = out + 6 * N + (size_t)task * 5;
            lo[0] = l0; lo[1] = l1; lo[2] = l2; lo[3] = l3; lo[4] = l4;
            float* po = out + 11 * N + (size_t)task * 5;
            po[0] = e0x * inv; po[1] = e1x * inv; po[2] = e2x * inv;
            po[3] = e3x * inv; po[4] = e4x * inv;
        }
    }
}

// ================= launch =================
extern "C" void kernel_launch(void* const* d_in, const int* in_sizes, int n_in,
                              void* d_out, int out_size) {
    const int*   questions  = (const int*)d_in[0];
    const int*   responses  = (const int*)d_in[1];
    const float* q_embed_w  = (const float*)d_in[2];
    const float* item_w     = (const float*)d_in[3];
    const float* vp_w       = (const float*)d_in[4];
    const float* vp_b       = (const float*)d_in[5];
    const float* key_mem    = (const float*)d_in[6];
    const float* init_mem   = (const float*)d_in[7];
    const float* er_w       = (const float*)d_in[8];
    const float* er_b       = (const float*)d_in[9];
    const float* ad_w       = (const float*)d_in[10];
    const float* ad_b       = (const float*)d_in[11];
    const float* sum_w      = (const float*)d_in[12];
    const float* sum_b      = (const float*)d_in[13];
    const float* th_w       = (const float*)d_in[14];
    const float* th_b       = (const float*)d_in[15];
    const float* al_w       = (const float*)d_in[16];
    const float* al_b       = (const float*)d_in[17];
    const float* be_w       = (const float*)d_in[18];
    const float* be_b       = (const float*)d_in[19];
    float* out = (float*)d_out;

    static int configured = 0;
    if (!configured) {
        cudaFuncSetAttribute(k_scan, cudaFuncAttributeMaxDynamicSharedMemorySize, SCAN_SMEM);
        cudaFuncSetAttribute(k_epi,  cudaFuncAttributeMaxDynamicSharedMemorySize, EPI_SMEM);
        configured = 1;
    }

    k_tab<<<QN, 512>>>(q_embed_w, key_mem, sum_w, sum_b, al_w, al_b, be_w, be_b,
                       item_w, vp_w, vp_b, er_w, er_b, ad_w, ad_b);
    k_scan<<<BN, 256, SCAN_SMEM>>>(questions, responses, init_mem);
    k_epi<<<(BN * SN) / TILE_T, 256, EPI_SMEM>>>(questions, sum_w, th_w, th_b, out);
}

// round 16
// speedup vs baseline: 1.0047x; 1.0047x over previous
#include <cuda_runtime.h>
#include <math.h>

#define QN 1000
#define KN 5
#define MN 50
#define DKN 64
#define DVN 128
#define DSN 50
#define BN 128
#define SN 2048

typedef unsigned long long ull;

// ---------- f32x2 helpers ----------
__device__ __forceinline__ ull ffma2(ull a, ull b, ull c) {
    ull d;
    asm("fma.rn.f32x2 %0, %1, %2, %3;" : "=l"(d) : "l"(a), "l"(b), "l"(c));
    return d;
}
__device__ __forceinline__ ull fpack2(float lo, float hi) {
    ull r;
    asm("mov.b64 %0, {%1, %2};" : "=l"(r) : "f"(lo), "f"(hi));
    return r;
}
__device__ __forceinline__ float2 funpack2(ull v) {
    float2 f;
    asm("mov.b64 {%0, %1}, %2;" : "=f"(f.x), "=f"(f.y) : "l"(v));
    return f;
}

// ---------- scratch ----------
__device__ float g_attn[QN * MN];
__device__ float g_sq[QN * DSN];
__device__ float g_alphat[QN];
__device__ float g_betat[QN * (KN - 1)];
__device__ float g_erase[QN * KN * DVN];
__device__ float g_addt[QN * KN * DVN];
__device__ float g_ce[KN * DVN];      // response-row contributions through er_w
__device__ float g_ca[KN * DVN];      // response-row contributions through ad_w
__device__ float g_reads[(size_t)BN * SN * DVN];

// ================= Kernel P: q-independent response contributions =================
// Ce[j][v] = sum_k vp_w[64+j][k] * er_w[k][v]  (and Ca via ad_w). 5 CTAs x 128.
__global__ void k_pre(const float* __restrict__ vp_w,
                      const float* __restrict__ er_w, const float* __restrict__ ad_w) {
    int j = blockIdx.x;
    int v = threadIdx.x;
    float ce = 0.f, ca = 0.f;
    #pragma unroll 8
    for (int k = 0; k < DVN; ++k) {
        float w = vp_w[(DKN + j) * DVN + k];
        ce += w * er_w[k * DVN + v];
        ca += w * ad_w[k * DVN + v];
    }
    g_ce[j * DVN + v] = ce;
    g_ca[j * DVN + v] = ca;
}

// ================= Kernel AB v4: merged tables, linear-decomposed e/a =================
// 1000 CTAs x 256 threads, thread = (v = t&127, h = t>>7).
// phase 1/2: value-embed BASE (no response part) split-k + qtab side jobs.
// phase 3: e_base/a_base accumulation with explicit 8-wide register load batches
// (16 outstanding LDG), split across h; then e[r] = e_base + sum_j rf(j,r)*Ce[j][v].
__global__ void __launch_bounds__(256)
k_tab(const float* __restrict__ qe_w, const float* __restrict__ key_mem,
      const float* __restrict__ sum_w, const float* __restrict__ sum_b,
      const float* __restrict__ al_w, const float* __restrict__ al_b,
      const float* __restrict__ be_w, const float* __restrict__ be_b,
      const float* __restrict__ item_w,
      const float* __restrict__ vp_w, const float* __restrict__ vp_b,
      const float* __restrict__ er_w, const float* __restrict__ er_b,
      const float* __restrict__ ad_w, const float* __restrict__ ad_b) {
    int q = blockIdx.x;
    int t = threadIdx.x;
    int v = t & 127;
    int h = t >> 7;                 // k-half
    __shared__ float qe[DKN];
    __shared__ float item[DKN];
    __shared__ float sl[MN], se[MN];
    __shared__ float base[DVN];
    __shared__ float bpart[DVN];
    __shared__ float part[DVN][2];

    if (t < DKN) {
        qe[t] = qe_w[q * DKN + t];
        item[t] = item_w[q * DKN + t];
    }
    __syncthreads();

    // ---- phase 1: base value-embed partial (question part only) ----
    float pb = (h == 0) ? vp_b[v] : 0.f;
    {
        int k0 = h * 32;
        #pragma unroll 8
        for (int k = k0; k < k0 + 32; ++k) pb += item[k] * vp_w[k * DVN + v];
    }
    if (h == 1) bpart[v] = pb;
    if (h == 1 && v < MN) {
        float acc = 0.f;
        #pragma unroll 8
        for (int k = 0; k < DKN; ++k) acc += qe[k] * key_mem[v * DKN + k];
        sl[v] = acc;
    }
    __syncthreads();

    // ---- phase 2: finalize base; softmax exp; sq/alpha/beta ----
    if (h == 0) base[v] = pb + bpart[v];
    if (h == 1 && v < MN) {
        float mx = -1e30f;
        for (int j = 0; j < MN; ++j) mx = fmaxf(mx, sl[j]);
        se[v] = expf(sl[v] - mx);
    }
    if (h == 0 && v < DSN) {
        float acc = sum_b[v];
        #pragma unroll 8
        for (int k = 0; k < DKN; ++k) acc += qe[k] * sum_w[(DVN + k) * DSN + v];
        g_sq[q * DSN + v] = acc;
    }
    if (h == 0 && v == 64) {
        float acc = al_b[0];
        for (int k = 0; k < DKN; ++k) acc += qe[k] * al_w[k];
        g_alphat[q] = fmaxf(acc, 0.f) + log1pf(expf(-fabsf(acc)));
    }
    if (h == 0 && v >= 68 && v < 68 + KN - 1) {
        int tt = v - 68;
        float acc = be_b[tt];
        for (int k = 0; k < DKN; ++k) acc += qe[k] * be_w[k * (KN - 1) + tt];
        g_betat[q * (KN - 1) + tt] = acc;
    }
    __syncthreads();

    if (h == 1 && v < MN) {
        float sm = 0.f;
        for (int j = 0; j < MN; ++j) sm += se[j];
        g_attn[q * MN + v] = se[v] / sm;
    }

    // ---- phase 3: e/a base accumulation, explicit 8-wide load batches ----
    float eacc = (h == 0) ? er_b[v] : 0.f;
    float aacc = (h == 0) ? ad_b[v] : 0.f;
    {
        int k0 = h * 64;
        for (int kb = 0; kb < 64; kb += 8) {
            float ew[8], aw[8], bs[8];
            #pragma unroll
            for (int i = 0; i < 8; ++i) {
                int k = k0 + kb + i;
                ew[i] = er_w[k * DVN + v];
                aw[i] = ad_w[k * DVN + v];
                bs[i] = base[k];
            }
            #pragma unroll
            for (int i = 0; i < 8; ++i) {
                eacc += bs[i] * ew[i];
                aacc += bs[i] * aw[i];
            }
        }
    }
    if (h == 1) { part[v][0] = eacc; part[v][1] = aacc; }
    __syncthreads();
    if (h == 0) {
        float eb = eacc + part[v][0];
        float ab = aacc + part[v][1];
        float ce[KN], ca[KN];
        #pragma unroll
        for (int j = 0; j < KN; ++j) {
            ce[j] = g_ce[j * DVN + v];
            ca[j] = g_ca[j * DVN + v];
        }
        #pragma unroll
        for (int r = 0; r < KN; ++r) {
            float er = eb, ar = ab;
            #pragma unroll
            for (int j = 0; j < KN; ++j) {
                float rf = fmaxf(1.f - fabsf((float)j - (float)r) * 0.25f, 0.f);
                er += rf * ce[j];
                ar += rf * ca[j];
            }
            g_erase[(q * KN + r) * DVN + v] = 1.f / (1.f + expf(-er));
            g_addt [(q * KN + r) * DVN + v] = tanhf(ar);
        }
    }
}

// ================= Kernel C: scan v8 verbatim (measured best) =================
#define ATT_PAD 52
#define SCAN_SMEM (QN * ATT_PAD * 4 + SN * 4 * 2)

__global__ void __launch_bounds__(256, 1)
k_scan(const int* __restrict__ questions, const int* __restrict__ responses,
       const float* __restrict__ init_mem) {
    extern __shared__ char smem_raw[];
    float* attn_sh = (float*)smem_raw;                       // QN*52 floats
    int*   aoff_sh = (int*)(smem_raw + QN * ATT_PAD * 4);    // q*52 per step
    int*   coff_sh = aoff_sh + SN;                           // (q*5+r)*128 per step

    int b = blockIdx.x, tid = threadIdx.x;
    int wid  = tid >> 5;
    int lane = tid & 31;
    int vsub = lane & 7;
    int mg   = lane >> 3;
    int vp   = wid * 8 + vsub;        // v-pair: v = 2vp, 2vp+1
    int mstart = mg * 13;

    for (int idx = tid; idx < QN * ATT_PAD; idx += 256) {
        int q = idx / ATT_PAD, m = idx - q * ATT_PAD;
        attn_sh[idx] = (m < MN) ? g_attn[q * MN + m] : 0.f;
    }
    for (int i = tid; i < SN; i += 256) {
        int q = questions[b * SN + i];
        int r = responses[b * SN + i];
        aoff_sh[i] = q * ATT_PAD;
        coff_sh[i] = (q * KN + r) * DVN;
    }

    ull mem[13];
    #pragma unroll
    for (int i = 0; i < 13; ++i) {
        int m = mstart + i;
        mem[i] = (m < MN) ? *(const ull*)(init_mem + m * DVN + 2 * vp) : 0ULL;
    }
    __syncthreads();

    // depth-2 erase/add prefetch pipeline
    int c0 = coff_sh[0];
    int c1 = coff_sh[1];
    ull e0  = *(const ull*)(g_erase + c0 + 2 * vp);
    ull ad0 = *(const ull*)(g_addt  + c0 + 2 * vp);
    ull e1  = *(const ull*)(g_erase + c1 + 2 * vp);
    ull ad1 = *(const ull*)(g_addt  + c1 + 2 * vp);

    // attention register prefetch: acur holds step-t row slice
    float acur[13];
    {
        int a0 = aoff_sh[0] + mstart;
        #pragma unroll
        for (int i = 0; i < 13; ++i) acur[i] = attn_sh[a0 + i];
    }

    float* outp = g_reads + (size_t)b * SN * DVN + 2 * vp;

    for (int t0 = 0; t0 < SN; t0 += 8) {
        float bx[8], by[8];
        #pragma unroll
        for (int j = 0; j < 8; ++j) {
            int t = t0 + j;
            ull e_cur = e0, ad_cur = ad0;
            e0 = e1; ad0 = ad1;
            int tp = (t + 2 < SN) ? t + 2 : SN - 1;
            int cp = coff_sh[tp];
            e1  = *(const ull*)(g_erase + cp + 2 * vp);
            ad1 = *(const ull*)(g_addt  + cp + 2 * vp);

            int anx = aoff_sh[(t + 1 < SN) ? t + 1 : SN - 1] + mstart;

            ull neg_e = e_cur ^ 0x8000000080000000ULL;
            ull r0 = 0ULL, r1 = 0ULL;
            #pragma unroll
            for (int i = 0; i < 13; ++i) {
                float a = acur[i];
                acur[i] = attn_sh[anx + i];              // prefetch next step's value
                ull ap = fpack2(a, a);
                ull tmp = ffma2(neg_e, mem[i], ad_cur);  // add - e*mem
                if (i & 1) r1 = ffma2(ap, mem[i], r1);
                else       r0 = ffma2(ap, mem[i], r0);
                mem[i] = ffma2(ap, tmp, mem[i]);         // mem += a*(add - e*mem)
            }
            float2 fa = funpack2(r0), fb = funpack2(r1);
            bx[j] = fa.x + fb.x;
            by[j] = fa.y + fb.y;
        }
        // pipelined reduction burst: 32 independent shfls
        #pragma unroll
        for (int j = 0; j < 8; ++j) {
            bx[j] += __shfl_xor_sync(0xffffffffu, bx[j], 8);
            by[j] += __shfl_xor_sync(0xffffffffu, by[j], 8);
        }
        #pragma unroll
        for (int j = 0; j < 8; ++j) {
            bx[j] += __shfl_xor_sync(0xffffffffu, bx[j], 16);
            by[j] += __shfl_xor_sync(0xffffffffu, by[j], 16);
        }
        if (mg == 0) {
            #pragma unroll
            for (int j = 0; j < 8; ++j)
                *(float2*)(outp + (size_t)(t0 + j) * DVN) = make_float2(bx[j], by[j]);
        }
    }
}

// ================= Kernel D: epilogue v9 verbatim (113.9us measured best) =================
#define TILE_T 256
#define W_STRIDE 26
#define EPI_SMEM ((DVN * W_STRIDE + 4) * 8)

__global__ void __launch_bounds__(256, 2)
k_epi(const int* __restrict__ questions,
      const float* __restrict__ sum_w,
      const float* __restrict__ th_w, const float* __restrict__ th_b,
      float* __restrict__ out) {
    extern __shared__ char smem_raw[];
    ull*   Wsu = (ull*)smem_raw;
    float* Wsf = (float*)Wsu;

    int tid = threadIdx.x;
    int t0 = blockIdx.x * TILE_T;

    // stage Ws (rows 0..127 of summary_w), zero-padded cols 50,51
    for (int i = tid; i < DVN * (2 * W_STRIDE); i += 256) {
        int v = i / (2 * W_STRIDE), j = i - v * (2 * W_STRIDE);
        Wsf[i] = (j < DSN) ? sum_w[v * DSN + j] : 0.f;
    }
    __syncthreads();

    int tg = tid >> 2;        // 0..63
    int jq = tid & 3;         // 0..3
    const float4* rows[4];
    #pragma unroll
    for (int i = 0; i < 4; ++i)
        rows[i] = (const float4*)(g_reads + (size_t)(t0 + tg + 64 * i) * DVN);
    const ull* wbase = Wsu + jq * 7;

    ull acc[4][7];
    #pragma unroll
    for (int i = 0; i < 4; ++i)
        #pragma unroll
        for (int k = 0; k < 7; ++k) acc[i][k] = 0ULL;

    float4 cur[4], nxt[4];
    #pragma unroll
    for (int i = 0; i < 4; ++i) cur[i] = __ldg(rows[i]);

    #pragma unroll 2
    for (int c = 0; c < DVN / 4; ++c) {
        if (c + 1 < DVN / 4) {
            #pragma unroll
            for (int i = 0; i < 4; ++i) nxt[i] = __ldg(rows[i] + c + 1);
        }
        #pragma unroll
        for (int s = 0; s < 4; ++s) {
            const ull* w = wbase + (4 * c + s) * W_STRIDE;
            ull rp[4];
            #pragma unroll
            for (int i = 0; i < 4; ++i) {
                float x = (&cur[i].x)[s];
                rp[i] = fpack2(x, x);
            }
            #pragma unroll
            for (int k = 0; k < 7; ++k) {
                ull wv = w[k];
                #pragma unroll
                for (int i = 0; i < 4; ++i)
                    acc[i][k] = ffma2(rp[i], wv, acc[i][k]);
            }
        }
        #pragma unroll
        for (int i = 0; i < 4; ++i) cur[i] = nxt[i];
    }

    float thb = th_b[0];
    const int N = BN * SN;

    #pragma unroll
    for (int i = 0; i < 4; ++i) {
        int task = t0 + tg + 64 * i;
        int qid = questions[task];
        float thp = 0.f;
        #pragma unroll
        for (int k = 0; k < 7; ++k) {
            int p = jq * 7 + k;
            if (p < 25) {
                float2 ac = funpack2(acc[i][k]);
                float2 sq2 = funpack2(*(const ull*)(g_sq + qid * DSN + 2 * p));
                float2 tw  = funpack2(*(const ull*)(th_w + 2 * p));
                float s0 = tanhf(ac.x + sq2.x);
                float s1 = tanhf(ac.y + sq2.y);
                thp += s0 * tw.x + s1 * tw.y;
            }
        }
        thp += __shfl_xor_sync(0xffffffffu, thp, 1);
        thp += __shfl_xor_sync(0xffffffffu, thp, 2);
        if (jq == 0) {
            float theta = tanhf(thp + thb);
            float alpha = g_alphat[qid];
            float inter = theta * alpha;
            float b0 = g_betat[qid * 4 + 0];
            float b1 = g_betat[qid * 4 + 1];
            float b2 = g_betat[qid * 4 + 2];
            float b3 = g_betat[qid * 4 + 3];
            float l0 = 0.f;
            float l1 = inter - b0;
            float l2 = l1 + inter - b1;
            float l3 = l2 + inter - b2;
            float l4 = l3 + inter - b3;
            float mx = fmaxf(fmaxf(fmaxf(l0, l1), fmaxf(l2, l3)), l4);
            float e0x = expf(l0 - mx), e1x = expf(l1 - mx), e2x = expf(l2 - mx);
            float e3x = expf(l3 - mx), e4x = expf(l4 - mx);
            float inv = 1.f / (e0x + e1x + e2x + e3x + e4x);

            out[task] = theta;
            out[N + task] = alpha;
            float* bo = out + 2 * N + (size_t)task * 4;
            bo[0] = b0; bo[1] = b1; bo[2] = b2; bo[3] = b3;
            float* lo = out + 6 * N + (size_t)task * 5;
            lo[0] = l0; lo[1] = l1; lo[2] = l2; lo[3] = l3; lo[4] = l4;
            float* po = out + 11 * N + (size_t)task * 5;
            po[0] = e0x * inv; po[1] = e1x * inv; po[2] = e2x * inv;
            po[3] = e3x * inv; po[4] = e4x * inv;
        }
    }
}

// ================= launch =================
extern "C" void kernel_launch(void* const* d_in, const int* in_sizes, int n_in,
                              void* d_out, int out_size) {
    const int*   questions  = (const int*)d_in[0];
    const int*   responses  = (const int*)d_in[1];
    const float* q_embed_w  = (const float*)d_in[2];
    const float* item_w     = (const float*)d_in[3];
    const float* vp_w       = (const float*)d_in[4];
    const float* vp_b       = (const float*)d_in[5];
    const float* key_mem    = (const float*)d_in[6];
    const float* init_mem   = (const float*)d_in[7];
    const float* er_w       = (const float*)d_in[8];
    const float* er_b       = (const float*)d_in[9];
    const float* ad_w       = (const float*)d_in[10];
    const float* ad_b       = (const float*)d_in[11];
    const float* sum_w      = (const float*)d_in[12];
    const float* sum_b      = (const float*)d_in[13];
    const float* th_w       = (const float*)d_in[14];
    const float* th_b       = (const float*)d_in[15];
    const float* al_w       = (const float*)d_in[16];
    const float* al_b       = (const float*)d_in[17];
    const float* be_w       = (const float*)d_in[18];
    const float* be_b       = (const float*)d_in[19];
    float* out = (float*)d_out;

    static int configured = 0;
    if (!configured) {
        cudaFuncSetAttribute(k_scan, cudaFuncAttributeMaxDynamicSharedMemorySize, SCAN_SMEM);
        cudaFuncSetAttribute(k_epi,  cudaFuncAttributeMaxDynamicSharedMemorySize, EPI_SMEM);
        configured = 1;
    }

    k_pre<<<KN, DVN>>>(vp_w, er_w, ad_w);
    k_tab<<<QN, 256>>>(q_embed_w, key_mem, sum_w, sum_b, al_w, al_b, be_w, be_b,
                       item_w, vp_w, vp_b, er_w, er_b, ad_w, ad_b);
    k_scan<<<BN, 256, SCAN_SMEM>>>(questions, responses, init_mem);
    k_epi<<<(BN * SN) / TILE_T, 256, EPI_SMEM>>>(questions, sum_w, th_w, th_b, out);
}